// round 4
// baseline (speedup 1.0000x reference)
#include <cuda_runtime.h>

#define NN 100000
#define NE 1600000

// Scratch (static device globals — no dynamic allocation allowed)
__device__ float4 g_zs[NN * 16];    // z * dinv   [N,64]
__device__ float4 g_agg1[NN * 16];  // layer-1 aggregation accumulator [N,64]
__device__ float4 g_x1[NN * 32];    // relu(gcn1) [N,128]
__device__ float4 g_hs2[NN * 16];   // (x1@W2)*dinv [N,64]
__device__ float  g_deg[NN];
__device__ float  g_dinv[NN];
__device__ int    g_layout;         // 1 = int64 pairs, 0 = int32

// Detect edge_index storage: int64 (odd 32-bit words all zero) vs int32.
__global__ void k_detect(const int* __restrict__ ei) {
    __shared__ int nz;
    if (threadIdx.x == 0) nz = 0;
    __syncthreads();
    if (ei[2 * threadIdx.x + 1] != 0) atomicOr(&nz, 1);
    __syncthreads();
    if (threadIdx.x == 0) g_layout = (nz == 0) ? 1 : 0;
}

__device__ __forceinline__ int edge_src(const int* __restrict__ ei, int e, int layout) {
    return layout ? ei[2 * e] : ei[e];
}
__device__ __forceinline__ int edge_dst(const int* __restrict__ ei, int e, int layout) {
    return layout ? ei[2 * (NE + e)] : ei[NE + e];
}

__global__ void k_zero_deg() {
    int i = blockIdx.x * 256 + threadIdx.x;
    if (i < NN) g_deg[i] = 0.0f;
}

// deg[d] += 1 for every edge target (self-loop +1 folded into k_dinv)
__global__ void k_deg(const int* __restrict__ ei) {
    int e = blockIdx.x * 256 + threadIdx.x;
    if (e < NE) {
        int layout = g_layout;
        int d = edge_dst(ei, e, layout);
        if ((unsigned)d < NN) atomicAdd(&g_deg[d], 1.0f);
    }
}

__global__ void k_dinv() {
    int i = blockIdx.x * 256 + threadIdx.x;
    if (i < NN) g_dinv[i] = rsqrtf(g_deg[i] + 1.0f);
}

// zs = z * dinv[row];  agg1 = zs  (self-loop contribution pre-seeded)
__global__ void k_scale_init(const float4* __restrict__ z4) {
    int u = blockIdx.x * 256 + threadIdx.x;  // exactly NN*16 units
    int node = u >> 4;
    float s = g_dinv[node];
    float4 v = __ldg(z4 + u);
    v.x *= s; v.y *= s; v.z *= s; v.w *= s;
    g_zs[u] = v;
    g_agg1[u] = v;
}

// Scatter-add 64 features per edge. 16 threads per edge (float4 each).
template <bool FIRST>
__global__ void k_scatter(const int* __restrict__ ei, float* __restrict__ dout) {
    int gt = blockIdx.x * 256 + threadIdx.x;  // exactly NE*16 threads
    int e = gt >> 4;
    int f = gt & 15;
    int layout = g_layout;
    int s = edge_src(ei, e, layout);
    int d = edge_dst(ei, e, layout);
    if ((unsigned)s >= NN || (unsigned)d >= NN) return;
    const float4* hs = FIRST ? (const float4*)g_zs : (const float4*)g_hs2;
    float* agg = FIRST ? (float*)g_agg1 : dout;
    float4 v = __ldg(hs + (size_t)s * 16 + f);
    float* p = agg + (size_t)d * 64 + f * 4;
    atomicAdd(p + 0, v.x);
    atomicAdd(p + 1, v.y);
    atomicAdd(p + 2, v.z);
    atomicAdd(p + 3, v.w);
}

// Dense GEMM: 32 rows/block, 256 threads, W staged in smem in K-chunks of 64.
// EPI==1: in = g_agg1 (rows scaled by dinv at load), out = relu(acc + b1) -> g_x1
// EPI==2: in = g_x1,  out = acc * dinv[row] -> g_hs2 AND d_out (agg2 seed)
template <int K, int N, int EPI>
__global__ void __launch_bounds__(256) k_gemm(const float* __restrict__ W,
                                              const float* __restrict__ bias,
                                              float* __restrict__ dout) {
    constexpr int TPR = N / 8;         // threads per row
    constexpr int GROUPS = 256 / TPR;  // row groups per block
    constexpr int R = 32 / GROUPS;     // rows per thread
    constexpr int KT = 64;

    __shared__ __align__(16) float Ws[KT * N];
    __shared__ __align__(16) float Rs[32][68];

    const float* in = (EPI == 1) ? (const float*)g_agg1 : (const float*)g_x1;

    int tid = threadIdx.x;
    int c = tid % TPR;
    int g = tid / TPR;
    int row0 = blockIdx.x * 32;

    float4 a0[R], a1[R];
#pragma unroll
    for (int i = 0; i < R; i++) {
        a0[i] = make_float4(0.f, 0.f, 0.f, 0.f);
        a1[i] = make_float4(0.f, 0.f, 0.f, 0.f);
    }

#pragma unroll
    for (int kt = 0; kt < K / KT; ++kt) {
        const float4* Wg = (const float4*)(W + kt * KT * N);
        float4* Ws4 = (float4*)Ws;
#pragma unroll
        for (int j = tid; j < KT * N / 4; j += 256) Ws4[j] = __ldg(Wg + j);
#pragma unroll
        for (int j = tid; j < 32 * 16; j += 256) {
            int r = j >> 4, c4 = j & 15;
            float4 v = __ldg((const float4*)(in + (size_t)(row0 + r) * K + kt * KT) + c4);
            if (EPI == 1) {
                float sc = g_dinv[row0 + r];
                v.x *= sc; v.y *= sc; v.z *= sc; v.w *= sc;
            }
            *(float4*)&Rs[r][c4 * 4] = v;
        }
        __syncthreads();

        const float4* Wr = (const float4*)Ws;
#pragma unroll 8
        for (int kk = 0; kk < KT; ++kk) {
            float4 w0 = Wr[kk * (N / 4) + 2 * c];
            float4 w1 = Wr[kk * (N / 4) + 2 * c + 1];
#pragma unroll
            for (int i = 0; i < R; ++i) {
                float zk = Rs[g * R + i][kk];
                a0[i].x += zk * w0.x; a0[i].y += zk * w0.y;
                a0[i].z += zk * w0.z; a0[i].w += zk * w0.w;
                a1[i].x += zk * w1.x; a1[i].y += zk * w1.y;
                a1[i].z += zk * w1.z; a1[i].w += zk * w1.w;
            }
        }
        __syncthreads();
    }

#pragma unroll
    for (int i = 0; i < R; ++i) {
        int grow = row0 + g * R + i;
        if (EPI == 1) {
            float4 bb0 = __ldg((const float4*)bias + 2 * c);
            float4 bb1 = __ldg((const float4*)bias + 2 * c + 1);
            float4 v0, v1;
            v0.x = fmaxf(a0[i].x + bb0.x, 0.f); v0.y = fmaxf(a0[i].y + bb0.y, 0.f);
            v0.z = fmaxf(a0[i].z + bb0.z, 0.f); v0.w = fmaxf(a0[i].w + bb0.w, 0.f);
            v1.x = fmaxf(a1[i].x + bb1.x, 0.f); v1.y = fmaxf(a1[i].y + bb1.y, 0.f);
            v1.z = fmaxf(a1[i].z + bb1.z, 0.f); v1.w = fmaxf(a1[i].w + bb1.w, 0.f);
            float4* op = (float4*)g_x1 + (size_t)grow * (N / 4);
            op[2 * c] = v0;
            op[2 * c + 1] = v1;
        } else {
            float sc = g_dinv[grow];
            float4 v0, v1;
            v0.x = a0[i].x * sc; v0.y = a0[i].y * sc; v0.z = a0[i].z * sc; v0.w = a0[i].w * sc;
            v1.x = a1[i].x * sc; v1.y = a1[i].y * sc; v1.z = a1[i].z * sc; v1.w = a1[i].w * sc;
            float4* h = (float4*)g_hs2 + (size_t)grow * (N / 4);
            float4* o = (float4*)dout + (size_t)grow * (N / 4);
            h[2 * c] = v0; h[2 * c + 1] = v1;
            o[2 * c] = v0; o[2 * c + 1] = v1;
        }
    }
}

// d_out = d_out * dinv[row] + b2
__global__ void k_finalize(float4* __restrict__ out, const float4* __restrict__ b2) {
    int u = blockIdx.x * 256 + threadIdx.x;  // exactly NN*16
    int node = u >> 4, f = u & 15;
    float s = g_dinv[node];
    float4 v = out[u];
    float4 b = __ldg(b2 + f);
    v.x = v.x * s + b.x; v.y = v.y * s + b.y;
    v.z = v.z * s + b.z; v.w = v.w * s + b.w;
    out[u] = v;
}

extern "C" void kernel_launch(void* const* d_in, const int* in_sizes, int n_in,
                              void* d_out, int out_size) {
    const float* z   = (const float*)d_in[0];
    const int* ei    = (const int*)d_in[1];   // int32 OR int64 pairs (detected)
    const float* W1  = (const float*)d_in[2];
    const float* b1  = (const float*)d_in[3];
    const float* W2  = (const float*)d_in[4];
    const float* b2  = (const float*)d_in[5];
    float* out = (float*)d_out;

    k_detect<<<1, 256>>>(ei);
    k_zero_deg<<<(NN + 255) / 256, 256>>>();
    k_deg<<<(NE + 255) / 256, 256>>>(ei);
    k_dinv<<<(NN + 255) / 256, 256>>>();
    k_scale_init<<<NN * 16 / 256, 256>>>((const float4*)z);
    k_scatter<true><<<NE * 16 / 256, 256>>>(ei, nullptr);
    k_gemm<64, 128, 1><<<NN / 32, 256>>>(W1, b1, nullptr);
    k_gemm<128, 64, 2><<<NN / 32, 256>>>(W2, nullptr, out);
    k_scatter<false><<<NE * 16 / 256, 256>>>(ei, out);
    k_finalize<<<NN * 16 / 256, 256>>>((float4*)out, (const float4*)b2);
}

// round 5
// speedup vs baseline: 1.5048x; 1.5048x over previous
#include <cuda_runtime.h>

#define NN 100000
#define NE 1600000

// Scratch (static device globals — no dynamic allocation allowed)
__device__ float4 g_zs[NN * 16];    // z * dinv   [N,64]
__device__ float4 g_agg1[NN * 16];  // layer-1 aggregation accumulator [N,64]
__device__ float4 g_x1[NN * 32];    // relu(gcn1) [N,128]
__device__ float4 g_hs2[NN * 16];   // (x1@W2)*dinv [N,64]
__device__ float  g_deg[NN];
__device__ float  g_dinv[NN];
__device__ int    g_layout;         // 1 = int64 pairs, 0 = int32

// Detect edge_index storage: int64 (odd 32-bit words all zero) vs int32.
__global__ void k_detect(const int* __restrict__ ei) {
    __shared__ int nz;
    if (threadIdx.x == 0) nz = 0;
    __syncthreads();
    if (ei[2 * threadIdx.x + 1] != 0) atomicOr(&nz, 1);
    __syncthreads();
    if (threadIdx.x == 0) g_layout = (nz == 0) ? 1 : 0;
}

__device__ __forceinline__ int edge_src(const int* __restrict__ ei, int e, int layout) {
    return layout ? ei[2 * e] : ei[e];
}
__device__ __forceinline__ int edge_dst(const int* __restrict__ ei, int e, int layout) {
    return layout ? ei[2 * (NE + e)] : ei[NE + e];
}

__global__ void k_zero_deg() {
    int i = blockIdx.x * 256 + threadIdx.x;
    if (i < NN) g_deg[i] = 0.0f;
}

// deg[d] += 1 for every edge target (self-loop +1 folded into k_dinv)
__global__ void k_deg(const int* __restrict__ ei) {
    int e = blockIdx.x * 256 + threadIdx.x;
    if (e < NE) {
        int layout = g_layout;
        int d = edge_dst(ei, e, layout);
        if ((unsigned)d < NN) atomicAdd(&g_deg[d], 1.0f);
    }
}

__global__ void k_dinv() {
    int i = blockIdx.x * 256 + threadIdx.x;
    if (i < NN) g_dinv[i] = rsqrtf(g_deg[i] + 1.0f);
}

// zs = z * dinv[row];  agg1 = zs  (self-loop contribution pre-seeded)
__global__ void k_scale_init(const float4* __restrict__ z4) {
    int u = blockIdx.x * 256 + threadIdx.x;  // exactly NN*16 units
    int node = u >> 4;
    float s = g_dinv[node];
    float4 v = __ldg(z4 + u);
    v.x *= s; v.y *= s; v.z *= s; v.w *= s;
    g_zs[u] = v;
    g_agg1[u] = v;
}

// Scatter-add 64 features per edge. 16 threads per edge, one float4 each.
// One 128-bit vector RED per thread (valid global addresses only).
template <bool FIRST>
__global__ void k_scatter(const int* __restrict__ ei, float4* __restrict__ dout) {
    int gt = blockIdx.x * 256 + threadIdx.x;  // exactly NE*16 threads
    int e = gt >> 4;
    int f = gt & 15;
    int layout = g_layout;
    int s = edge_src(ei, e, layout);
    int d = edge_dst(ei, e, layout);
    if ((unsigned)s >= NN || (unsigned)d >= NN) return;
    const float4* hs = FIRST ? (const float4*)g_zs : (const float4*)g_hs2;
    float4* agg = FIRST ? (float4*)g_agg1 : dout;
    float4 v = __ldg(hs + (size_t)s * 16 + f);
    atomicAdd(agg + (size_t)d * 16 + f, v);   // RED.E.ADD.F32.128
}

// Dense GEMM: 32 rows/block, 256 threads, W staged in smem in K-chunks of 64.
// EPI==1: in = g_agg1 (rows scaled by dinv at load), out = relu(acc + b1) -> g_x1
// EPI==2: in = g_x1,  out = acc * dinv[row] -> g_hs2 AND d_out (agg2 seed)
template <int K, int N, int EPI>
__global__ void __launch_bounds__(256) k_gemm(const float* __restrict__ W,
                                              const float* __restrict__ bias,
                                              float* __restrict__ dout) {
    constexpr int TPR = N / 8;         // threads per row
    constexpr int GROUPS = 256 / TPR;  // row groups per block
    constexpr int R = 32 / GROUPS;     // rows per thread
    constexpr int KT = 64;

    __shared__ __align__(16) float Ws[KT * N];
    __shared__ __align__(16) float Rs[32][68];

    const float* in = (EPI == 1) ? (const float*)g_agg1 : (const float*)g_x1;

    int tid = threadIdx.x;
    int c = tid % TPR;
    int g = tid / TPR;
    int row0 = blockIdx.x * 32;

    float4 a0[R], a1[R];
#pragma unroll
    for (int i = 0; i < R; i++) {
        a0[i] = make_float4(0.f, 0.f, 0.f, 0.f);
        a1[i] = make_float4(0.f, 0.f, 0.f, 0.f);
    }

#pragma unroll
    for (int kt = 0; kt < K / KT; ++kt) {
        const float4* Wg = (const float4*)(W + kt * KT * N);
        float4* Ws4 = (float4*)Ws;
#pragma unroll
        for (int j = tid; j < KT * N / 4; j += 256) Ws4[j] = __ldg(Wg + j);
#pragma unroll
        for (int j = tid; j < 32 * 16; j += 256) {
            int r = j >> 4, c4 = j & 15;
            float4 v = __ldg((const float4*)(in + (size_t)(row0 + r) * K + kt * KT) + c4);
            if (EPI == 1) {
                float sc = g_dinv[row0 + r];
                v.x *= sc; v.y *= sc; v.z *= sc; v.w *= sc;
            }
            *(float4*)&Rs[r][c4 * 4] = v;
        }
        __syncthreads();

        const float4* Wr = (const float4*)Ws;
#pragma unroll 8
        for (int kk = 0; kk < KT; ++kk) {
            float4 w0 = Wr[kk * (N / 4) + 2 * c];
            float4 w1 = Wr[kk * (N / 4) + 2 * c + 1];
#pragma unroll
            for (int i = 0; i < R; ++i) {
                float zk = Rs[g * R + i][kk];
                a0[i].x += zk * w0.x; a0[i].y += zk * w0.y;
                a0[i].z += zk * w0.z; a0[i].w += zk * w0.w;
                a1[i].x += zk * w1.x; a1[i].y += zk * w1.y;
                a1[i].z += zk * w1.z; a1[i].w += zk * w1.w;
            }
        }
        __syncthreads();
    }

#pragma unroll
    for (int i = 0; i < R; ++i) {
        int grow = row0 + g * R + i;
        if (EPI == 1) {
            float4 bb0 = __ldg((const float4*)bias + 2 * c);
            float4 bb1 = __ldg((const float4*)bias + 2 * c + 1);
            float4 v0, v1;
            v0.x = fmaxf(a0[i].x + bb0.x, 0.f); v0.y = fmaxf(a0[i].y + bb0.y, 0.f);
            v0.z = fmaxf(a0[i].z + bb0.z, 0.f); v0.w = fmaxf(a0[i].w + bb0.w, 0.f);
            v1.x = fmaxf(a1[i].x + bb1.x, 0.f); v1.y = fmaxf(a1[i].y + bb1.y, 0.f);
            v1.z = fmaxf(a1[i].z + bb1.z, 0.f); v1.w = fmaxf(a1[i].w + bb1.w, 0.f);
            float4* op = (float4*)g_x1 + (size_t)grow * (N / 4);
            op[2 * c] = v0;
            op[2 * c + 1] = v1;
        } else {
            float sc = g_dinv[grow];
            float4 v0, v1;
            v0.x = a0[i].x * sc; v0.y = a0[i].y * sc; v0.z = a0[i].z * sc; v0.w = a0[i].w * sc;
            v1.x = a1[i].x * sc; v1.y = a1[i].y * sc; v1.z = a1[i].z * sc; v1.w = a1[i].w * sc;
            float4* h = (float4*)g_hs2 + (size_t)grow * (N / 4);
            float4* o = (float4*)dout + (size_t)grow * (N / 4);
            h[2 * c] = v0; h[2 * c + 1] = v1;
            o[2 * c] = v0; o[2 * c + 1] = v1;
        }
    }
}

// d_out = d_out * dinv[row] + b2
__global__ void k_finalize(float4* __restrict__ out, const float4* __restrict__ b2) {
    int u = blockIdx.x * 256 + threadIdx.x;  // exactly NN*16
    int node = u >> 4, f = u & 15;
    float s = g_dinv[node];
    float4 v = out[u];
    float4 b = __ldg(b2 + f);
    v.x = v.x * s + b.x; v.y = v.y * s + b.y;
    v.z = v.z * s + b.z; v.w = v.w * s + b.w;
    out[u] = v;
}

extern "C" void kernel_launch(void* const* d_in, const int* in_sizes, int n_in,
                              void* d_out, int out_size) {
    const float* z   = (const float*)d_in[0];
    const int* ei    = (const int*)d_in[1];   // int32 OR int64 pairs (detected)
    const float* W1  = (const float*)d_in[2];
    const float* b1  = (const float*)d_in[3];
    const float* W2  = (const float*)d_in[4];
    const float* b2  = (const float*)d_in[5];
    float* out = (float*)d_out;

    k_detect<<<1, 256>>>(ei);
    k_zero_deg<<<(NN + 255) / 256, 256>>>();
    k_deg<<<(NE + 255) / 256, 256>>>(ei);
    k_dinv<<<(NN + 255) / 256, 256>>>();
    k_scale_init<<<NN * 16 / 256, 256>>>((const float4*)z);
    k_scatter<true><<<NE * 16 / 256, 256>>>(ei, nullptr);
    k_gemm<64, 128, 1><<<NN / 32, 256>>>(W1, b1, nullptr);
    k_gemm<128, 64, 2><<<NN / 32, 256>>>(W2, nullptr, out);
    k_scatter<false><<<NE * 16 / 256, 256>>>(ei, (float4*)out);
    k_finalize<<<NN * 16 / 256, 256>>>((float4*)out, (const float4*)b2);
}

// round 7
// speedup vs baseline: 1.9267x; 1.2804x over previous
#include <cuda_runtime.h>

#define NN 100000
#define NE 1600000
#define SCAN_B 1024
#define SCAN_NB ((NN + SCAN_B - 1) / SCAN_B)   // 98

// Scratch (static device globals — no dynamic allocation allowed)
__device__ float4 g_zs[NN * 16];    // z * dinv   [N,64]
__device__ float4 g_agg1[NN * 16];  // layer-1 aggregation result [N,64]
__device__ float4 g_x1[NN * 32];    // relu(gcn1) [N,128]
__device__ float4 g_hs2[NN * 16];   // (x1@W2)*dinv [N,64]
__device__ float  g_dinv[NN];
__device__ int    g_cnt[NN];        // in-degree (edges only)
__device__ int    g_off[NN];        // CSR row offsets (exclusive prefix of cnt)
__device__ int    g_cur[NN];        // mutable cursor for permute
__device__ int    g_esrc[NE];       // src indices sorted by dst
__device__ int    g_bsum[128];      // scan block sums
__device__ int    g_layout;         // 1 = int64 pairs, 0 = int32

// Detect edge_index storage: int64 (odd 32-bit words all zero) vs int32.
__global__ void k_detect(const int* __restrict__ ei) {
    __shared__ int nz;
    if (threadIdx.x == 0) nz = 0;
    __syncthreads();
    if (ei[2 * threadIdx.x + 1] != 0) atomicOr(&nz, 1);
    __syncthreads();
    if (threadIdx.x == 0) g_layout = (nz == 0) ? 1 : 0;
}

__device__ __forceinline__ int edge_src(const int* __restrict__ ei, int e, int layout) {
    return layout ? ei[2 * e] : ei[e];
}
__device__ __forceinline__ int edge_dst(const int* __restrict__ ei, int e, int layout) {
    return layout ? ei[2 * (NE + e)] : ei[NE + e];
}

__global__ void k_zero_cnt() {
    int i = blockIdx.x * 256 + threadIdx.x;
    if (i < NN) g_cnt[i] = 0;
}

// Histogram of destinations (int atomics)
__global__ void k_hist(const int* __restrict__ ei) {
    int e = blockIdx.x * 256 + threadIdx.x;
    if (e < NE) {
        int d = edge_dst(ei, e, g_layout);
        if ((unsigned)d < NN) atomicAdd(&g_cnt[d], 1);
    }
}

// Block-level exclusive scan (Hillis-Steele), emits per-block totals.
__global__ void k_scan1() {
    __shared__ int sh[SCAN_B];
    int i = blockIdx.x * SCAN_B + threadIdx.x;
    int v = (i < NN) ? g_cnt[i] : 0;
    sh[threadIdx.x] = v;
    __syncthreads();
#pragma unroll
    for (int ofs = 1; ofs < SCAN_B; ofs <<= 1) {
        int t = (threadIdx.x >= ofs) ? sh[threadIdx.x - ofs] : 0;
        __syncthreads();
        sh[threadIdx.x] += t;
        __syncthreads();
    }
    if (i < NN) g_off[i] = sh[threadIdx.x] - v;   // exclusive
    if (threadIdx.x == SCAN_B - 1) g_bsum[blockIdx.x] = sh[SCAN_B - 1];
}

// Scan the block sums (single block, 128 >= SCAN_NB)
__global__ void k_scan2() {
    __shared__ int sh[128];
    int v = (threadIdx.x < SCAN_NB) ? g_bsum[threadIdx.x] : 0;
    sh[threadIdx.x] = v;
    __syncthreads();
#pragma unroll
    for (int ofs = 1; ofs < 128; ofs <<= 1) {
        int t = (threadIdx.x >= ofs) ? sh[threadIdx.x - ofs] : 0;
        __syncthreads();
        sh[threadIdx.x] += t;
        __syncthreads();
    }
    g_bsum[threadIdx.x] = sh[threadIdx.x] - v;    // exclusive
}

// Finalize offsets, seed cursors, compute dinv (deg = cnt + self-loop)
__global__ void k_scan3() {
    int i = blockIdx.x * 256 + threadIdx.x;
    if (i < NN) {
        int o = g_off[i] + g_bsum[i >> 10];
        g_off[i] = o;
        g_cur[i] = o;
        g_dinv[i] = rsqrtf((float)g_cnt[i] + 1.0f);
    }
}

// Counting-sort edges by destination (order within a segment irrelevant)
__global__ void k_permute(const int* __restrict__ ei) {
    int e = blockIdx.x * 256 + threadIdx.x;
    if (e < NE) {
        int layout = g_layout;
        int s = edge_src(ei, e, layout);
        int d = edge_dst(ei, e, layout);
        if ((unsigned)s >= NN || (unsigned)d >= NN) return;
        int pos = atomicAdd(&g_cur[d], 1);
        g_esrc[pos] = s;
    }
}

// zs = z * dinv[row]
__global__ void k_scale_init(const float4* __restrict__ z4) {
    int u = blockIdx.x * 256 + threadIdx.x;  // exactly NN*16 units
    int node = u >> 4;
    float s = g_dinv[node];
    float4 v = __ldg(z4 + u);
    v.x *= s; v.y *= s; v.z *= s; v.w *= s;
    g_zs[u] = v;
}

// Gather-side segment sum: 16 threads per node, one float4 column each.
// FIRST: in = g_zs (pre-scaled by dinv[src]), out = g_agg1 (self-loop seeded);
//        dinv[dst] post-scale fused into gemm1's row load.
// else : in = g_hs2 (pre-scaled by dinv[src] in gemm2 epilogue),
//        out = d_out with fused (*dinv[dst] + b2) epilogue.
template <bool FIRST>
__global__ void k_gather(float4* __restrict__ dout, const float4* __restrict__ b2v) {
    int gt = blockIdx.x * 256 + threadIdx.x;  // exactly NN*16 threads
    int node = gt >> 4;
    int f = gt & 15;
    const float4* hs = FIRST ? (const float4*)g_zs : (const float4*)g_hs2;
    float4 acc = __ldg(hs + (size_t)node * 16 + f);  // self-loop seed
    int j = g_off[node];
    int end = j + g_cnt[node];
    // 2-way software pipeline for a little MLP
    for (; j + 2 <= end; j += 2) {
        int s0 = __ldg(&g_esrc[j]);
        int s1 = __ldg(&g_esrc[j + 1]);
        float4 v0 = __ldg(hs + (size_t)s0 * 16 + f);
        float4 v1 = __ldg(hs + (size_t)s1 * 16 + f);
        acc.x += v0.x + v1.x; acc.y += v0.y + v1.y;
        acc.z += v0.z + v1.z; acc.w += v0.w + v1.w;
    }
    if (j < end) {
        int s0 = __ldg(&g_esrc[j]);
        float4 v0 = __ldg(hs + (size_t)s0 * 16 + f);
        acc.x += v0.x; acc.y += v0.y; acc.z += v0.z; acc.w += v0.w;
    }
    if (FIRST) {
        g_agg1[(size_t)node * 16 + f] = acc;
    } else {
        float sc = g_dinv[node];
        float4 b = __ldg(b2v + f);
        acc.x = acc.x * sc + b.x; acc.y = acc.y * sc + b.y;
        acc.z = acc.z * sc + b.z; acc.w = acc.w * sc + b.w;
        dout[(size_t)node * 16 + f] = acc;
    }
}

// Dense GEMM: 32 rows/block, 256 threads, W staged in smem in K-chunks of 64.
// EPI==1: in = g_agg1 (rows scaled by dinv at load), out = relu(acc + b1) -> g_x1
// EPI==2: in = g_x1,  out = acc * dinv[row] -> g_hs2   (pre-scale by dinv[src]!)
template <int K, int N, int EPI>
__global__ void __launch_bounds__(256) k_gemm(const float* __restrict__ W,
                                              const float* __restrict__ bias) {
    constexpr int TPR = N / 8;         // threads per row
    constexpr int GROUPS = 256 / TPR;  // row groups per block
    constexpr int R = 32 / GROUPS;     // rows per thread
    constexpr int KT = 64;

    __shared__ __align__(16) float Ws[KT * N];
    __shared__ __align__(16) float Rs[32][68];

    const float* in = (EPI == 1) ? (const float*)g_agg1 : (const float*)g_x1;

    int tid = threadIdx.x;
    int c = tid % TPR;
    int g = tid / TPR;
    int row0 = blockIdx.x * 32;

    float4 a0[R], a1[R];
#pragma unroll
    for (int i = 0; i < R; i++) {
        a0[i] = make_float4(0.f, 0.f, 0.f, 0.f);
        a1[i] = make_float4(0.f, 0.f, 0.f, 0.f);
    }

#pragma unroll
    for (int kt = 0; kt < K / KT; ++kt) {
        const float4* Wg = (const float4*)(W + kt * KT * N);
        float4* Ws4 = (float4*)Ws;
#pragma unroll
        for (int j = tid; j < KT * N / 4; j += 256) Ws4[j] = __ldg(Wg + j);
#pragma unroll
        for (int j = tid; j < 32 * 16; j += 256) {
            int r = j >> 4, c4 = j & 15;
            float4 v = __ldg((const float4*)(in + (size_t)(row0 + r) * K + kt * KT) + c4);
            if (EPI == 1) {
                float sc = g_dinv[row0 + r];
                v.x *= sc; v.y *= sc; v.z *= sc; v.w *= sc;
            }
            *(float4*)&Rs[r][c4 * 4] = v;
        }
        __syncthreads();

        const float4* Wr = (const float4*)Ws;
#pragma unroll 8
        for (int kk = 0; kk < KT; ++kk) {
            float4 w0 = Wr[kk * (N / 4) + 2 * c];
            float4 w1 = Wr[kk * (N / 4) + 2 * c + 1];
#pragma unroll
            for (int i = 0; i < R; ++i) {
                float zk = Rs[g * R + i][kk];
                a0[i].x += zk * w0.x; a0[i].y += zk * w0.y;
                a0[i].z += zk * w0.z; a0[i].w += zk * w0.w;
                a1[i].x += zk * w1.x; a1[i].y += zk * w1.y;
                a1[i].z += zk * w1.z; a1[i].w += zk * w1.w;
            }
        }
        __syncthreads();
    }

#pragma unroll
    for (int i = 0; i < R; ++i) {
        int grow = row0 + g * R + i;
        if (EPI == 1) {
            float4 bb0 = __ldg((const float4*)bias + 2 * c);
            float4 bb1 = __ldg((const float4*)bias + 2 * c + 1);
            float4 v0, v1;
            v0.x = fmaxf(a0[i].x + bb0.x, 0.f); v0.y = fmaxf(a0[i].y + bb0.y, 0.f);
            v0.z = fmaxf(a0[i].z + bb0.z, 0.f); v0.w = fmaxf(a0[i].w + bb0.w, 0.f);
            v1.x = fmaxf(a1[i].x + bb1.x, 0.f); v1.y = fmaxf(a1[i].y + bb1.y, 0.f);
            v1.z = fmaxf(a1[i].z + bb1.z, 0.f); v1.w = fmaxf(a1[i].w + bb1.w, 0.f);
            float4* op = (float4*)g_x1 + (size_t)grow * (N / 4);
            op[2 * c] = v0;
            op[2 * c + 1] = v1;
        } else {
            // hs2 = (x1@W2) * dinv[row]  — per-source pre-scale (REQUIRED)
            float sc = g_dinv[grow];
            float4 v0, v1;
            v0.x = a0[i].x * sc; v0.y = a0[i].y * sc; v0.z = a0[i].z * sc; v0.w = a0[i].w * sc;
            v1.x = a1[i].x * sc; v1.y = a1[i].y * sc; v1.z = a1[i].z * sc; v1.w = a1[i].w * sc;
            float4* h = (float4*)g_hs2 + (size_t)grow * (N / 4);
            h[2 * c] = v0;
            h[2 * c + 1] = v1;
        }
    }
}

extern "C" void kernel_launch(void* const* d_in, const int* in_sizes, int n_in,
                              void* d_out, int out_size) {
    const float* z   = (const float*)d_in[0];
    const int* ei    = (const int*)d_in[1];   // int32 OR int64 pairs (detected)
    const float* W1  = (const float*)d_in[2];
    const float* b1  = (const float*)d_in[3];
    const float* W2  = (const float*)d_in[4];
    const float* b2  = (const float*)d_in[5];
    float* out = (float*)d_out;

    k_detect<<<1, 256>>>(ei);
    k_zero_cnt<<<(NN + 255) / 256, 256>>>();
    k_hist<<<(NE + 255) / 256, 256>>>(ei);
    k_scan1<<<SCAN_NB, SCAN_B>>>();
    k_scan2<<<1, 128>>>();
    k_scan3<<<(NN + 255) / 256, 256>>>();
    k_permute<<<(NE + 255) / 256, 256>>>(ei);
    k_scale_init<<<NN * 16 / 256, 256>>>((const float4*)z);
    k_gather<true><<<NN * 16 / 256, 256>>>(nullptr, nullptr);
    k_gemm<64, 128, 1><<<NN / 32, 256>>>(W1, b1);
    k_gemm<128, 64, 2><<<NN / 32, 256>>>(W2, nullptr);
    k_gather<false><<<NN * 16 / 256, 256>>>((float4*)out, (const float4*)b2);
}

// round 8
// speedup vs baseline: 3.1840x; 1.6525x over previous
#include <cuda_runtime.h>

#define NN 100000
#define NE 1600000
#define SCAN_B 1024
#define SCAN_NB ((NN + SCAN_B - 1) / SCAN_B)   // 98

// Scratch (static device globals — no dynamic allocation allowed)
__device__ float4 g_zs[NN * 16];    // z * dinv   [N,64]
__device__ float4 g_agg1[NN * 16];  // layer-1 aggregation result [N,64]
__device__ float4 g_x1[NN * 32];    // relu(gcn1) [N,128]
__device__ float4 g_hs2[NN * 16];   // (x1@W2)*dinv [N,64]
__device__ float  g_dinv[NN];
__device__ int    g_cnt[NN];        // in-degree (edges only)
__device__ int    g_off[NN];        // CSR row offsets (exclusive prefix of cnt)
__device__ int    g_cur[NN];        // mutable cursor for permute
__device__ int    g_esrc[NE];       // src indices sorted by dst
__device__ int    g_bsum[128];      // scan block sums
__device__ int    g_layout;         // 1 = int64 pairs, 0 = int32

// Detect edge_index storage: int64 (odd 32-bit words all zero) vs int32.
__global__ void k_detect(const int* __restrict__ ei) {
    __shared__ int nz;
    if (threadIdx.x == 0) nz = 0;
    __syncthreads();
    if (ei[2 * threadIdx.x + 1] != 0) atomicOr(&nz, 1);
    __syncthreads();
    if (threadIdx.x == 0) g_layout = (nz == 0) ? 1 : 0;
}

__device__ __forceinline__ int edge_src(const int* __restrict__ ei, int e, int layout) {
    return layout ? ei[2 * e] : ei[e];
}
__device__ __forceinline__ int edge_dst(const int* __restrict__ ei, int e, int layout) {
    return layout ? ei[2 * (NE + e)] : ei[NE + e];
}

__global__ void k_zero_cnt() {
    int i = blockIdx.x * 256 + threadIdx.x;
    if (i < NN) g_cnt[i] = 0;
}

// Histogram of destinations (int atomics)
__global__ void k_hist(const int* __restrict__ ei) {
    int e = blockIdx.x * 256 + threadIdx.x;
    if (e < NE) {
        int d = edge_dst(ei, e, g_layout);
        if ((unsigned)d < NN) atomicAdd(&g_cnt[d], 1);
    }
}

// Block-level exclusive scan (Hillis-Steele), emits per-block totals.
__global__ void k_scan1() {
    __shared__ int sh[SCAN_B];
    int i = blockIdx.x * SCAN_B + threadIdx.x;
    int v = (i < NN) ? g_cnt[i] : 0;
    sh[threadIdx.x] = v;
    __syncthreads();
#pragma unroll
    for (int ofs = 1; ofs < SCAN_B; ofs <<= 1) {
        int t = (threadIdx.x >= ofs) ? sh[threadIdx.x - ofs] : 0;
        __syncthreads();
        sh[threadIdx.x] += t;
        __syncthreads();
    }
    if (i < NN) g_off[i] = sh[threadIdx.x] - v;   // exclusive
    if (threadIdx.x == SCAN_B - 1) g_bsum[blockIdx.x] = sh[SCAN_B - 1];
}

// Scan the block sums (single block, 128 >= SCAN_NB)
__global__ void k_scan2() {
    __shared__ int sh[128];
    int v = (threadIdx.x < SCAN_NB) ? g_bsum[threadIdx.x] : 0;
    sh[threadIdx.x] = v;
    __syncthreads();
#pragma unroll
    for (int ofs = 1; ofs < 128; ofs <<= 1) {
        int t = (threadIdx.x >= ofs) ? sh[threadIdx.x - ofs] : 0;
        __syncthreads();
        sh[threadIdx.x] += t;
        __syncthreads();
    }
    g_bsum[threadIdx.x] = sh[threadIdx.x] - v;    // exclusive
}

// Finalize offsets, seed cursors, compute dinv (deg = cnt + self-loop)
__global__ void k_scan3() {
    int i = blockIdx.x * 256 + threadIdx.x;
    if (i < NN) {
        int o = g_off[i] + g_bsum[i >> 10];
        g_off[i] = o;
        g_cur[i] = o;
        g_dinv[i] = rsqrtf((float)g_cnt[i] + 1.0f);
    }
}

// Counting-sort edges by destination (order within a segment irrelevant)
__global__ void k_permute(const int* __restrict__ ei) {
    int e = blockIdx.x * 256 + threadIdx.x;
    if (e < NE) {
        int layout = g_layout;
        int s = edge_src(ei, e, layout);
        int d = edge_dst(ei, e, layout);
        if ((unsigned)s >= NN || (unsigned)d >= NN) return;
        int pos = atomicAdd(&g_cur[d], 1);
        g_esrc[pos] = s;
    }
}

// zs = z * dinv[row]
__global__ void k_scale_init(const float4* __restrict__ z4) {
    int u = blockIdx.x * 256 + threadIdx.x;  // exactly NN*16 units
    int node = u >> 4;
    float s = g_dinv[node];
    float4 v = __ldg(z4 + u);
    v.x *= s; v.y *= s; v.z *= s; v.w *= s;
    g_zs[u] = v;
}

// Gather-side segment sum: 16 threads per node, one float4 column each.
// FIRST: in = g_zs (pre-scaled by dinv[src]), out = g_agg1 (self-loop seeded);
//        dinv[dst] post-scale fused into gemm1's row load.
// else : in = g_hs2 (pre-scaled by dinv[src] in gemm2 epilogue),
//        out = d_out with fused (*dinv[dst] + b2) epilogue.
template <bool FIRST>
__global__ void k_gather(float4* __restrict__ dout, const float4* __restrict__ b2v) {
    int gt = blockIdx.x * 256 + threadIdx.x;  // exactly NN*16 threads
    int node = gt >> 4;
    int f = gt & 15;
    const float4* hs = FIRST ? (const float4*)g_zs : (const float4*)g_hs2;
    float4 acc = __ldg(hs + (size_t)node * 16 + f);  // self-loop seed
    int j = g_off[node];
    int end = j + g_cnt[node];
    // 4-way software pipeline for MLP
    for (; j + 4 <= end; j += 4) {
        int s0 = __ldg(&g_esrc[j]);
        int s1 = __ldg(&g_esrc[j + 1]);
        int s2 = __ldg(&g_esrc[j + 2]);
        int s3 = __ldg(&g_esrc[j + 3]);
        float4 v0 = __ldg(hs + (size_t)s0 * 16 + f);
        float4 v1 = __ldg(hs + (size_t)s1 * 16 + f);
        float4 v2 = __ldg(hs + (size_t)s2 * 16 + f);
        float4 v3 = __ldg(hs + (size_t)s3 * 16 + f);
        acc.x += (v0.x + v1.x) + (v2.x + v3.x);
        acc.y += (v0.y + v1.y) + (v2.y + v3.y);
        acc.z += (v0.z + v1.z) + (v2.z + v3.z);
        acc.w += (v0.w + v1.w) + (v2.w + v3.w);
    }
    for (; j < end; ++j) {
        int s0 = __ldg(&g_esrc[j]);
        float4 v0 = __ldg(hs + (size_t)s0 * 16 + f);
        acc.x += v0.x; acc.y += v0.y; acc.z += v0.z; acc.w += v0.w;
    }
    if (FIRST) {
        g_agg1[(size_t)node * 16 + f] = acc;
    } else {
        float sc = g_dinv[node];
        float4 b = __ldg(b2v + f);
        acc.x = acc.x * sc + b.x; acc.y = acc.y * sc + b.y;
        acc.z = acc.z * sc + b.z; acc.w = acc.w * sc + b.w;
        dout[(size_t)node * 16 + f] = acc;
    }
}

// Dense GEMM: ROWS rows/block, 256 threads, R=4 rows/thread, float4 zk loads.
// EPI==1: in = g_agg1 (rows scaled by dinv at load), out = relu(acc + b1) -> g_x1
// EPI==2: in = g_x1,  out = acc * dinv[row] -> g_hs2   (pre-scale by dinv[src])
template <int K, int N, int ROWS, int EPI>
__global__ void __launch_bounds__(256) k_gemm(const float* __restrict__ W,
                                              const float* __restrict__ bias) {
    constexpr int TPR = N / 8;          // threads per row-group (8 outputs each)
    constexpr int GROUPS = 256 / TPR;   // row groups per block
    constexpr int R = ROWS / GROUPS;    // rows per thread (4)
    constexpr int KT = 32;
    constexpr int RST = KT + 4;         // float stride, keeps float4 alignment

    __shared__ __align__(16) float Ws[KT * N];
    __shared__ __align__(16) float Rs[ROWS * RST];

    const float* in = (EPI == 1) ? (const float*)g_agg1 : (const float*)g_x1;

    int tid = threadIdx.x;
    int c = tid % TPR;
    int g = tid / TPR;
    int row0 = blockIdx.x * ROWS;

    float4 a0[R], a1[R];
#pragma unroll
    for (int i = 0; i < R; i++) {
        a0[i] = make_float4(0.f, 0.f, 0.f, 0.f);
        a1[i] = make_float4(0.f, 0.f, 0.f, 0.f);
    }

#pragma unroll
    for (int kt = 0; kt < K / KT; ++kt) {
        const float4* Wg = (const float4*)(W + kt * KT * N);
        float4* Ws4 = (float4*)Ws;
#pragma unroll
        for (int j = tid; j < KT * N / 4; j += 256) Ws4[j] = __ldg(Wg + j);
#pragma unroll
        for (int j = tid; j < ROWS * (KT / 4); j += 256) {
            int r = j / (KT / 4), c4 = j % (KT / 4);
            int grow = row0 + r;
            if (grow >= NN) grow = NN - 1;
            float4 v = __ldg((const float4*)(in + (size_t)grow * K + kt * KT) + c4);
            if (EPI == 1) {
                float sc = g_dinv[grow];
                v.x *= sc; v.y *= sc; v.z *= sc; v.w *= sc;
            }
            *(float4*)&Rs[r * RST + c4 * 4] = v;
        }
        __syncthreads();

        const float4* Wr = (const float4*)Ws;
#pragma unroll
        for (int kk4 = 0; kk4 < KT / 4; ++kk4) {
            float4 zk[R];
#pragma unroll
            for (int i = 0; i < R; ++i)
                zk[i] = *(const float4*)&Rs[(g * R + i) * RST + kk4 * 4];
#pragma unroll
            for (int kc = 0; kc < 4; ++kc) {
                float4 w0 = Wr[(kk4 * 4 + kc) * (N / 4) + 2 * c];
                float4 w1 = Wr[(kk4 * 4 + kc) * (N / 4) + 2 * c + 1];
#pragma unroll
                for (int i = 0; i < R; ++i) {
                    float z = (kc == 0) ? zk[i].x : (kc == 1) ? zk[i].y
                             : (kc == 2) ? zk[i].z : zk[i].w;
                    a0[i].x += z * w0.x; a0[i].y += z * w0.y;
                    a0[i].z += z * w0.z; a0[i].w += z * w0.w;
                    a1[i].x += z * w1.x; a1[i].y += z * w1.y;
                    a1[i].z += z * w1.z; a1[i].w += z * w1.w;
                }
            }
        }
        __syncthreads();
    }

#pragma unroll
    for (int i = 0; i < R; ++i) {
        int grow = row0 + g * R + i;
        if (grow >= NN) continue;
        if (EPI == 1) {
            float4 bb0 = __ldg((const float4*)bias + 2 * c);
            float4 bb1 = __ldg((const float4*)bias + 2 * c + 1);
            float4 v0, v1;
            v0.x = fmaxf(a0[i].x + bb0.x, 0.f); v0.y = fmaxf(a0[i].y + bb0.y, 0.f);
            v0.z = fmaxf(a0[i].z + bb0.z, 0.f); v0.w = fmaxf(a0[i].w + bb0.w, 0.f);
            v1.x = fmaxf(a1[i].x + bb1.x, 0.f); v1.y = fmaxf(a1[i].y + bb1.y, 0.f);
            v1.z = fmaxf(a1[i].z + bb1.z, 0.f); v1.w = fmaxf(a1[i].w + bb1.w, 0.f);
            float4* op = (float4*)g_x1 + (size_t)grow * (N / 4);
            op[2 * c] = v0;
            op[2 * c + 1] = v1;
        } else {
            float sc = g_dinv[grow];
            float4 v0, v1;
            v0.x = a0[i].x * sc; v0.y = a0[i].y * sc; v0.z = a0[i].z * sc; v0.w = a0[i].w * sc;
            v1.x = a1[i].x * sc; v1.y = a1[i].y * sc; v1.z = a1[i].z * sc; v1.w = a1[i].w * sc;
            float4* h = (float4*)g_hs2 + (size_t)grow * (N / 4);
            h[2 * c] = v0;
            h[2 * c + 1] = v1;
        }
    }
}

extern "C" void kernel_launch(void* const* d_in, const int* in_sizes, int n_in,
                              void* d_out, int out_size) {
    const float* z   = (const float*)d_in[0];
    const int* ei    = (const int*)d_in[1];   // int32 OR int64 pairs (detected)
    const float* W1  = (const float*)d_in[2];
    const float* b1  = (const float*)d_in[3];
    const float* W2  = (const float*)d_in[4];
    const float* b2  = (const float*)d_in[5];
    float* out = (float*)d_out;

    k_detect<<<1, 256>>>(ei);
    k_zero_cnt<<<(NN + 255) / 256, 256>>>();
    k_hist<<<(NE + 255) / 256, 256>>>(ei);
    k_scan1<<<SCAN_NB, SCAN_B>>>();
    k_scan2<<<1, 128>>>();
    k_scan3<<<(NN + 255) / 256, 256>>>();
    k_permute<<<(NE + 255) / 256, 256>>>(ei);
    k_scale_init<<<NN * 16 / 256, 256>>>((const float4*)z);
    k_gather<true><<<NN * 16 / 256, 256>>>(nullptr, nullptr);
    k_gemm<64, 128, 64, 1><<<(NN + 63) / 64, 256>>>(W1, b1);
    k_gemm<128, 64, 128, 2><<<(NN + 127) / 128, 256>>>(W2, nullptr);
    k_gather<false><<<NN * 16 / 256, 256>>>((float4*)out, (const float4*)b2);
}